// round 1
// baseline (speedup 1.0000x reference)
#include <cuda_runtime.h>
#include <cstdint>

// ---------------- problem constants ----------------
#define BN_SEQ 256          // b*n = 2*128 sequences
#define P_LEN  32           // patches (scan length)
#define DM     256          // d_model
#define DS     16           // d_state
#define DR     16           // dt_rank
#define M_ROWS (BN_SEQ*P_LEN)   // 8192

// ---------------- scratch (static device memory; no allocs) ----------------
__device__ float g_xr  [M_ROWS*DM];            // (8192,256)  8MB
__device__ float g_xz  [3*M_ROWS*512];         // 48MB
__device__ float g_xc  [3*M_ROWS*DM];          // 24MB
__device__ float g_dbc [3*M_ROWS*48];          // 4.5MB
__device__ float g_y   [3*M_ROWS*DM];          // 24MB
__device__ float g_outs[3*M_ROWS*DM];          // 24MB
__device__ float g_hf  [BN_SEQ*P_LEN*DM];      // 8MB
__device__ float g_hb  [BN_SEQ*P_LEN*DM];      // 8MB

__device__ __forceinline__ float sigmoidf_(float x){ return 1.f/(1.f+__expf(-x)); }

// ---------------- zero hf/hb (must re-zero each graph replay) --------------
__global__ void zero_state_kernel() {
    int i = blockIdx.x*blockDim.x + threadIdx.x;
    if (i < BN_SEQ*P_LEN*DM) { g_hf[i] = 0.f; g_hb[i] = 0.f; }
}

// ---------------- x (b,P,n,D) -> xr (b*n, P, D) ----------------------------
__global__ void transpose_x_kernel(const float* __restrict__ x) {
    int t = blockIdx.x*256 + threadIdx.x;            // over 2*32*128*256
    int d  = t & 255;
    int p  = (t >> 8) & 31;
    int bn = t >> 13;                                 // 0..255
    int ni = bn & 127;
    int bi = bn >> 7;
    g_xr[t] = x[(((size_t)(bi*32 + p))*128 + ni)*256 + d];
}

// ---------------- generic fp32 GEMM: C = A @ B^T  (A: MxK, B: NxK) ---------
// 64x64 tile, BK=16, 256 threads, 4x4 microtile. Batched over blockIdx.z.
__global__ __launch_bounds__(256) void gemm64_kernel(
    const float* __restrict__ A, size_t sAz,
    const float* __restrict__ B, size_t sBz,
    float* __restrict__ C, size_t sCz,
    int M, int N, int K)
{
    __shared__ float As[16][64];
    __shared__ float Bs[16][64];
    const float* Az = A + (size_t)blockIdx.z * sAz;
    const float* Bz = B + (size_t)blockIdx.z * sBz;
    float*       Cz = C + (size_t)blockIdx.z * sCz;
    int m0 = blockIdx.x * 64, n0 = blockIdx.y * 64;
    int tid = threadIdx.x;
    int ar = tid >> 2;            // 0..63
    int ac = (tid & 3) * 4;       // 0,4,8,12
    int tx = tid & 15, ty = tid >> 4;
    float acc[4][4] = {};
    for (int k0 = 0; k0 < K; k0 += 16) {
        float4 av = *(const float4*)(Az + (size_t)(m0 + ar)*K + k0 + ac);
        As[ac+0][ar]=av.x; As[ac+1][ar]=av.y; As[ac+2][ar]=av.z; As[ac+3][ar]=av.w;
        float4 bv = make_float4(0.f,0.f,0.f,0.f);
        if (n0 + ar < N) bv = *(const float4*)(Bz + (size_t)(n0 + ar)*K + k0 + ac);
        Bs[ac+0][ar]=bv.x; Bs[ac+1][ar]=bv.y; Bs[ac+2][ar]=bv.z; Bs[ac+3][ar]=bv.w;
        __syncthreads();
        #pragma unroll
        for (int kk = 0; kk < 16; kk++) {
            float4 a = *(const float4*)&As[kk][ty*4];
            float4 b = *(const float4*)&Bs[kk][tx*4];
            acc[0][0]+=a.x*b.x; acc[0][1]+=a.x*b.y; acc[0][2]+=a.x*b.z; acc[0][3]+=a.x*b.w;
            acc[1][0]+=a.y*b.x; acc[1][1]+=a.y*b.y; acc[1][2]+=a.y*b.z; acc[1][3]+=a.y*b.w;
            acc[2][0]+=a.z*b.x; acc[2][1]+=a.z*b.y; acc[2][2]+=a.z*b.z; acc[2][3]+=a.z*b.w;
            acc[3][0]+=a.w*b.x; acc[3][1]+=a.w*b.y; acc[3][2]+=a.w*b.z; acc[3][3]+=a.w*b.w;
        }
        __syncthreads();
    }
    int m = m0 + ty*4, n = n0 + tx*4;
    #pragma unroll
    for (int i = 0; i < 4; i++)
        #pragma unroll
        for (int j = 0; j < 4; j++)
            if (n + j < N) Cz[(size_t)(m+i)*N + (n+j)] = acc[i][j];
}

// ---------------- depthwise causal conv (width 4) + SiLU -------------------
__global__ void conv_silu_kernel(const float* __restrict__ conv_w,
                                 const float* __restrict__ conv_b) {
    int k = blockIdx.y;
    int t = blockIdx.x*256 + threadIdx.x;   // over 8192*256
    int d = t & 255;
    int m = t >> 8;
    int bn = m >> 5, p = m & 31;
    const float* xzk = g_xz + (size_t)k*M_ROWS*512;
    float acc = conv_b[k*DM + d];
    #pragma unroll
    for (int j = 0; j < 4; j++) {
        int pp = p + j - 3;
        if (pp >= 0) acc += xzk[((size_t)(bn*32 + pp))*512 + d] * conv_w[(k*DM + d)*4 + j];
    }
    g_xc[(size_t)k*M_ROWS*DM + (size_t)m*DM + d] = acc * sigmoidf_(acc);
}

// ---------------- fused dt-proj + softplus + selective scan + gate ---------
// one block per (sequence bn, mamba block k); thread = channel d; h in regs
__global__ __launch_bounds__(256) void scan_kernel(
    const float* __restrict__ dt_w, const float* __restrict__ dt_b,
    const float* __restrict__ A_log, const float* __restrict__ D_skip)
{
    int bn = blockIdx.x, k = blockIdx.y, d = threadIdx.x;
    const float* dbck = g_dbc + (size_t)k*M_ROWS*48;
    const float* xck  = g_xc  + (size_t)k*M_ROWS*DM;
    const float* xzk  = g_xz  + (size_t)k*M_ROWS*512;
    float*       yk   = g_y   + (size_t)k*M_ROWS*DM;

    float Arow[DS], dtw[DR];
    #pragma unroll
    for (int s = 0; s < DS; s++) Arow[s] = -expf(A_log[((size_t)k*DM + d)*DS + s]);
    #pragma unroll
    for (int r = 0; r < DR; r++) dtw[r] = dt_w[((size_t)k*DM + d)*DR + r];
    float dtb = dt_b[k*DM + d];
    float dsk = D_skip[k*DM + d];

    __shared__ float sdbc[48];
    float h[DS];
    #pragma unroll
    for (int s = 0; s < DS; s++) h[s] = 0.f;

    for (int p = 0; p < P_LEN; p++) {
        int m = bn*P_LEN + p;
        __syncthreads();
        if (d < 48) sdbc[d] = dbck[(size_t)m*48 + d];
        __syncthreads();
        float xcv = xck[(size_t)m*DM + d];
        float zgv = xzk[(size_t)m*512 + 256 + d];
        float pre = dtb;
        #pragma unroll
        for (int r = 0; r < DR; r++) pre += sdbc[r] * dtw[r];
        float dt = (pre > 20.f) ? pre : log1pf(__expf(pre));   // softplus
        float dx = dt * xcv;
        float yv = 0.f;
        #pragma unroll
        for (int s = 0; s < DS; s++) {
            h[s] = __expf(dt * Arow[s]) * h[s] + dx * sdbc[16 + s];
            yv += h[s] * sdbc[32 + s];
        }
        float tot = yv + xcv * dsk;
        yk[(size_t)m*DM + d] = tot * (zgv * sigmoidf_(zgv));
    }
}

// ---------------- one GRU step (both directions), fused GEMM+gates ---------
// grid (8, 8, 2): 32x32 output tiles, z=direction. K=512 (concat of hf/hb rows).
__global__ __launch_bounds__(256) void gru_step_kernel(
    int p,
    const float* __restrict__ wf, const float* __restrict__ bf,
    const float* __restrict__ wb, const float* __restrict__ bb)
{
    const float* out0 = g_outs;
    const float* out1 = g_outs + (size_t)M_ROWS*DM;
    const float* out2 = g_outs + 2*(size_t)M_ROWS*DM;

    int dir = blockIdx.z;
    int pos, pos1, pos2;
    const float* W; const float* bias; float* O;
    if (dir == 0) {           // forward: concat(hf[p-1], hb[p]) @ wf^T
        pos = p; pos1 = p - 1; pos2 = p;
        W = wf; bias = bf; O = g_hf;
    } else {                  // backward at bp: concat(hf[bp], hb[bp+1]) @ wb^T
        pos = P_LEN - 1 - p; pos1 = pos; pos2 = min(pos + 1, P_LEN - 1);
        W = wb; bias = bb; O = g_hb;
    }
    bool hasHi = (p > 0);

    __shared__ float As[32][32];
    __shared__ float Bs[32][32];
    int tid = threadIdx.x;
    int r = tid >> 3;            // 0..31
    int c = (tid & 7) * 4;       // 0..28
    int tx = tid & 15, ty = tid >> 4;
    int m0 = blockIdx.x * 32, n0 = blockIdx.y * 32;
    float acc[2][2] = {};

    if (hasHi) {
        for (int k0 = 0; k0 < 512; k0 += 32) {
            int kg = k0 + c;
            float4 av;
            if (kg < 256) av = *(const float4*)(g_hf + ((size_t)(m0+r)*P_LEN + pos1)*DM + kg);
            else          av = *(const float4*)(g_hb + ((size_t)(m0+r)*P_LEN + pos2)*DM + (kg-256));
            As[c+0][r]=av.x; As[c+1][r]=av.y; As[c+2][r]=av.z; As[c+3][r]=av.w;
            float4 wv = *(const float4*)(W + (size_t)(n0+r)*512 + kg);
            Bs[c+0][r]=wv.x; Bs[c+1][r]=wv.y; Bs[c+2][r]=wv.z; Bs[c+3][r]=wv.w;
            __syncthreads();
            #pragma unroll
            for (int kk = 0; kk < 32; kk++) {
                float2 a = *(const float2*)&As[kk][ty*2];
                float2 b = *(const float2*)&Bs[kk][tx*2];
                acc[0][0]+=a.x*b.x; acc[0][1]+=a.x*b.y;
                acc[1][0]+=a.y*b.x; acc[1][1]+=a.y*b.y;
            }
            __syncthreads();
        }
    }

    #pragma unroll
    for (int i = 0; i < 2; i++)
        #pragma unroll
        for (int j = 0; j < 2; j++) {
            int gm = m0 + ty*2 + i;
            int n  = n0 + tx*2 + j;
            float hi = hasHi ? (acc[i][j] + bias[n]) : 0.f;
            size_t o = ((size_t)gm*P_LEN + pos)*DM + n;
            float zv  = sigmoidf_(out0[o]);
            float rv  = sigmoidf_(out1[o]);
            float hcv = tanhf(out2[o]);
            float hn  = tanhf(hcv + rv*hi);
            O[o] = (1.f - zv)*hi + zv*hn;
        }
}

// ---------------- combined = hf[:, -1] + hb[:, 0];  LayerNorm --------------
__global__ void final_ln_kernel(const float* __restrict__ ln_g,
                                const float* __restrict__ ln_b,
                                float* __restrict__ out)
{
    int row = blockIdx.x, d = threadIdx.x;     // 256 rows x 256 dims
    float v = g_hf[((size_t)row*P_LEN + (P_LEN-1))*DM + d]
            + g_hb[((size_t)row*P_LEN + 0)*DM + d];
    float s = v, q = v*v;
    #pragma unroll
    for (int o = 16; o > 0; o >>= 1) {
        s += __shfl_down_sync(0xffffffffu, s, o);
        q += __shfl_down_sync(0xffffffffu, q, o);
    }
    __shared__ float ssum[8], ssq[8];
    __shared__ float mu_s, rstd_s;
    int w = d >> 5, l = d & 31;
    if (l == 0) { ssum[w] = s; ssq[w] = q; }
    __syncthreads();
    if (d == 0) {
        float ts = 0.f, tq = 0.f;
        for (int i = 0; i < 8; i++) { ts += ssum[i]; tq += ssq[i]; }
        float mu = ts / 256.f;
        float var = tq / 256.f - mu*mu;
        mu_s = mu; rstd_s = rsqrtf(var + 1e-5f);
    }
    __syncthreads();
    out[(size_t)row*DM + d] = (v - mu_s) * rstd_s * ln_g[d] + ln_b[d];
}

// ---------------- launcher ----------------
extern "C" void kernel_launch(void* const* d_in, const int* in_sizes, int n_in,
                              void* d_out, int out_size)
{
    const float* x       = (const float*)d_in[0];
    const float* in_w    = (const float*)d_in[1];
    const float* conv_w  = (const float*)d_in[2];
    const float* conv_b  = (const float*)d_in[3];
    const float* xproj_w = (const float*)d_in[4];
    const float* dt_w    = (const float*)d_in[5];
    const float* dt_b    = (const float*)d_in[6];
    const float* A_log   = (const float*)d_in[7];
    const float* D_skip  = (const float*)d_in[8];
    const float* out_w   = (const float*)d_in[9];
    const float* wf      = (const float*)d_in[10];
    const float* bf      = (const float*)d_in[11];
    const float* wb      = (const float*)d_in[12];
    const float* bb      = (const float*)d_in[13];
    const float* ln_g    = (const float*)d_in[14];
    const float* ln_b    = (const float*)d_in[15];
    float* out = (float*)d_out;

    void* p;
    cudaGetSymbolAddress(&p, g_xr);   float* xr   = (float*)p;
    cudaGetSymbolAddress(&p, g_xz);   float* xz   = (float*)p;
    cudaGetSymbolAddress(&p, g_xc);   float* xc   = (float*)p;
    cudaGetSymbolAddress(&p, g_dbc);  float* dbc  = (float*)p;
    cudaGetSymbolAddress(&p, g_y);    float* yb   = (float*)p;
    cudaGetSymbolAddress(&p, g_outs); float* outs = (float*)p;

    // 1. reset recurrent state (graph replays require this every call)
    zero_state_kernel<<<(BN_SEQ*P_LEN*DM + 255)/256, 256>>>();

    // 2. x -> xr
    transpose_x_kernel<<<(M_ROWS*DM)/256, 256>>>(x);

    // 3. xz = xr @ in_w^T   (M=8192, N=512, K=256), batched over 3 blocks
    gemm64_kernel<<<dim3(128, 8, 3), 256>>>(xr, 0, in_w, (size_t)512*256,
                                            xz, (size_t)M_ROWS*512, M_ROWS, 512, 256);

    // 4. causal conv + SiLU
    conv_silu_kernel<<<dim3((M_ROWS*DM)/256, 3), 256>>>(conv_w, conv_b);

    // 5. dbc = xc @ xproj_w^T  (N=48)
    gemm64_kernel<<<dim3(128, 1, 3), 256>>>(xc, (size_t)M_ROWS*DM, xproj_w, (size_t)48*256,
                                            dbc, (size_t)M_ROWS*48, M_ROWS, 48, 256);

    // 6. fused dt + selective scan + skip + SiLU gate -> g_y
    scan_kernel<<<dim3(BN_SEQ, 3), 256>>>(dt_w, dt_b, A_log, D_skip);

    // 7. outs = y @ out_w^T  (N=256, K=256)
    gemm64_kernel<<<dim3(128, 4, 3), 256>>>(yb, (size_t)M_ROWS*DM, out_w, (size_t)256*256,
                                            outs, (size_t)M_ROWS*DM, M_ROWS, 256, 256);

    // 8. interleaved bidirectional GRU, 32 sequential steps
    for (int step = 0; step < P_LEN; step++)
        gru_step_kernel<<<dim3(8, 8, 2), 256>>>(step, wf, bf, wb, bb);

    // 9. combine + LayerNorm
    final_ln_kernel<<<BN_SEQ, 256>>>(ln_g, ln_b, out);
}